// round 1
// baseline (speedup 1.0000x reference)
#include <cuda_runtime.h>

// Problem constants
#define B_TOTAL 32768
#define NUM_MID 6
#define P       8            // patches per block
#define NTHREADS 224         // 8*25 = 200 active, padded to 7 warps

// SMEM layout (floats)
#define H_PLANE   49                 // 7x7 zero-padded plane
#define H_BUF     (P*25*H_PLANE)     // 9800
#define W_BUF     (25*25*9)          // 5625
#define SMEM_FLOATS (2*H_BUF + W_BUF + 32 + P*75 + P*18)
#define SMEM_BYTES  (SMEM_FLOATS*4)

template<int CIN>
__device__ __forceinline__ void conv_step(const float* __restrict__ hin,  // [CIN][49] this patch
                                          const float* __restrict__ w,    // [CIN][9] this oc
                                          float bias,
                                          float* __restrict__ hout)       // [49] this (patch,oc)
{
    float acc[25];
    #pragma unroll
    for (int i = 0; i < 25; i++) acc[i] = bias;

    #pragma unroll 1
    for (int ic = 0; ic < CIN; ic++) {
        const float* hp = hin + ic * H_PLANE;
        float v[49];
        #pragma unroll
        for (int i = 0; i < 49; i++) v[i] = hp[i];
        const float* wp = w + ic * 9;
        float ww[9];
        #pragma unroll
        for (int t = 0; t < 9; t++) ww[t] = wp[t];

        #pragma unroll
        for (int dy = 0; dy < 3; dy++)
            #pragma unroll
            for (int dx = 0; dx < 3; dx++)
                #pragma unroll
                for (int y = 0; y < 5; y++)
                    #pragma unroll
                    for (int x = 0; x < 5; x++)
                        acc[y*5+x] = fmaf(ww[dy*3+dx], v[(y+dy)*7 + (x+dx)], acc[y*5+x]);
    }

    #pragma unroll
    for (int y = 0; y < 5; y++)
        #pragma unroll
        for (int x = 0; x < 5; x++)
            hout[(y+1)*7 + (x+1)] = fmaxf(acc[y*5+x], 0.0f);
}

__global__ __launch_bounds__(NTHREADS, 2)
void Kpcnn_49160195670356_kernel(const float* __restrict__ gin,
                                 const float* __restrict__ w0,
                                 const float* __restrict__ b0,
                                 const float* __restrict__ wmid,
                                 const float* __restrict__ bmid,
                                 const float* __restrict__ wlast,
                                 const float* __restrict__ blast,
                                 const float* __restrict__ wpost,
                                 const float* __restrict__ bpost,
                                 float* __restrict__ gout)
{
    extern __shared__ float smem[];
    float* hA      = smem;                 // P*25*49
    float* hB      = hA + H_BUF;           // P*25*49
    float* wbuf    = hB + H_BUF;           // 5625
    float* bbuf    = wbuf + W_BUF;         // 32 (25 used)
    float* inpRGB  = bbuf + 32;            // P*75
    float* colorsS = inpRGB + P*75;        // P*18

    const int tid = threadIdx.x;
    const int p   = tid / 25;
    const int oc  = tid % 25;
    const bool act = (tid < P*25);
    const long pg = (long)blockIdx.x * P;

    // 1. zero both activation buffers (borders must stay 0 forever)
    for (int i = tid; i < 2*H_BUF; i += NTHREADS) hA[i] = 0.0f;
    // load conv0 weights/bias
    for (int i = tid; i < 25*8*9; i += NTHREADS) wbuf[i] = w0[i];
    if (tid < 25) bbuf[tid] = b0[tid];
    __syncthreads();

    // 2. stage input into hB planes 0..7 (padded interior) + inpRGB copy
    for (int i = tid; i < P*8*25; i += NTHREADS) {
        int pp  = i / 200;
        int rem = i % 200;
        int c   = rem / 25;
        int pos = rem % 25;
        float v = gin[(pg + pp)*200 + c*25 + pos];
        int y = pos / 5, x = pos % 5;
        hB[(pp*25 + c)*H_PLANE + (y+1)*7 + (x+1)] = v;
        if (c < 3) inpRGB[pp*75 + c*25 + pos] = v;
    }
    __syncthreads();

    // 3. conv0: hB (8 ch) -> hA, relu
    if (act)
        conv_step<8>(hB + p*25*H_PLANE, wbuf + oc*72, bbuf[oc],
                     hA + (p*25 + oc)*H_PLANE);

    // 4. mid layers, ping-pong hA <-> hB
    float* bufs[2] = { hA, hB };
    int cur = 0;   // current activations in bufs[cur]
    #pragma unroll 1
    for (int layer = 0; layer < NUM_MID; layer++) {
        __syncthreads();   // prior compute done (reads of wbuf + writes of hout complete)
        const float* wg = wmid + (long)layer * W_BUF;
        for (int i = tid; i < W_BUF; i += NTHREADS) wbuf[i] = wg[i];
        if (tid < 25) bbuf[tid] = bmid[layer*25 + tid];
        __syncthreads();
        if (act)
            conv_step<25>(bufs[cur] + p*25*H_PLANE, wbuf + oc*225, bbuf[oc],
                          bufs[cur^1] + (p*25 + oc)*H_PLANE);
        cur ^= 1;
    }

    __syncthreads();

    // 5. colors (postconv, VALID 5x5 on first 3 input channels) + stage wlast
    for (int i = tid; i < 6*25*9; i += NTHREADS) wbuf[i] = wlast[i];
    if (tid < 6) bbuf[tid] = blast[tid];
    if (act && oc < 18) {
        float a = bpost[oc];
        const float* wp2 = wpost + oc*75;
        const float* ip  = inpRGB + p*75;
        #pragma unroll
        for (int k = 0; k < 75; k++) a = fmaf(__ldg(wp2 + k), ip[k], a);
        colorsS[p*18 + oc] = a;
    }
    __syncthreads();

    // 6. last conv (25->6) per position, softmax over 6, einsum with colors
    if (act) {
        const int j = oc;            // position 0..24
        const int y = j / 5, x = j % 5;
        const float* hfin = bufs[cur] + p*25*H_PLANE;

        float s[6];
        #pragma unroll
        for (int w_ = 0; w_ < 6; w_++) s[w_] = bbuf[w_];

        #pragma unroll 1
        for (int ic = 0; ic < 25; ic++) {
            const float* hp = hfin + ic*H_PLANE;
            float v[9];
            #pragma unroll
            for (int dy = 0; dy < 3; dy++)
                #pragma unroll
                for (int dx = 0; dx < 3; dx++)
                    v[dy*3+dx] = hp[(y+dy)*7 + (x+dx)];
            #pragma unroll
            for (int w_ = 0; w_ < 6; w_++) {
                const float* wp = wbuf + (w_*25 + ic)*9;
                #pragma unroll
                for (int t = 0; t < 9; t++)
                    s[w_] = fmaf(wp[t], v[t], s[w_]);
            }
        }

        // softmax over the 6 weight channels
        float m = s[0];
        #pragma unroll
        for (int w_ = 1; w_ < 6; w_++) m = fmaxf(m, s[w_]);
        float e[6];
        float sum = 0.0f;
        #pragma unroll
        for (int w_ = 0; w_ < 6; w_++) { e[w_] = __expf(s[w_] - m); sum += e[w_]; }
        const float inv = 1.0f / sum;

        const long ob = (pg + p) * 75;
        #pragma unroll
        for (int c = 0; c < 3; c++) {
            float r = 0.0f;
            #pragma unroll
            for (int w_ = 0; w_ < 6; w_++)
                r = fmaf(colorsS[p*18 + c*6 + w_], e[w_], r);
            gout[ob + c*25 + j] = r * inv;
        }
    }
}

extern "C" void kernel_launch(void* const* d_in, const int* in_sizes, int n_in,
                              void* d_out, int out_size)
{
    const float* gin   = (const float*)d_in[0];
    const float* w0    = (const float*)d_in[1];
    const float* b0    = (const float*)d_in[2];
    const float* wmid  = (const float*)d_in[3];
    const float* bmid  = (const float*)d_in[4];
    const float* wlast = (const float*)d_in[5];
    const float* blast = (const float*)d_in[6];
    const float* wpost = (const float*)d_in[7];
    const float* bpost = (const float*)d_in[8];
    float* gout = (float*)d_out;

    cudaFuncSetAttribute(Kpcnn_49160195670356_kernel,
                         cudaFuncAttributeMaxDynamicSharedMemorySize, SMEM_BYTES);

    Kpcnn_49160195670356_kernel<<<B_TOTAL / P, NTHREADS, SMEM_BYTES>>>(
        gin, w0, b0, wmid, bmid, wlast, blast, wpost, bpost, gout);
}

// round 2
// speedup vs baseline: 2.0540x; 2.0540x over previous
#include <cuda_runtime.h>

typedef unsigned long long u64;

#define B_TOTAL  32768
#define NUM_MID  6
#define PPB      16          // patches per block (8 pairs)
#define NPAIR    8
#define NTHREADS 224         // 8*25 = 200 active

// SMEM layout (floats)
#define PLANE    50                         // 25 positions x 2 (pair-interleaved)
#define PBLK     (25*PLANE)                 // 1250 floats per (pair) block of 25 channels
#define H_BUF    (NPAIR*PBLK)               // 10000
#define W_BUF    7500                       // mid weights padded: [25][25][12]
#define WPOST_OFF 2400                      // conv0 occupies [0,2400); wpost at [2400,3750)
#define SMEM_FLOATS (2*H_BUF + W_BUF + 64 + 2*NPAIR*18)
#define SMEM_BYTES  (SMEM_FLOATS*4)

// ---- f32x2 helpers ----
__device__ __forceinline__ u64 f2pack(float lo, float hi) {
    u64 r; asm("mov.b64 %0,{%1,%2};" : "=l"(r) : "f"(lo), "f"(hi)); return r;
}
__device__ __forceinline__ u64 f2bcast(float v) { return f2pack(v, v); }
__device__ __forceinline__ void f2unpack(u64 a, float& lo, float& hi) {
    asm("mov.b64 {%0,%1},%2;" : "=f"(lo), "=f"(hi) : "l"(a));
}
__device__ __forceinline__ u64 f2fma(u64 a, u64 b, u64 c) {
    u64 d; asm("fma.rn.f32x2 %0,%1,%2,%3;" : "=l"(d) : "l"(a), "l"(b), "l"(c)); return d;
}

// conv 3x3 SAME on a 5x5 plane, pair-packed, zero-pad handled at compile time.
// hin: [CIN][PLANE] for this pair; wrow: [CIN][12] for this oc; hout: [PLANE]
template<int CIN>
__device__ __forceinline__ void conv_pair(const float* __restrict__ hin,
                                          const float* __restrict__ wrow,
                                          float bias,
                                          float* __restrict__ hout)
{
    u64 acc[25];
    const u64 b2 = f2bcast(bias);
    #pragma unroll
    for (int i = 0; i < 25; i++) acc[i] = b2;

    #pragma unroll 1
    for (int ic = 0; ic < CIN; ic++) {
        const u64* hp = (const u64*)(hin + ic * PLANE);
        const float* wp = wrow + ic * 12;
        float4 wa = *(const float4*)(wp);
        float4 wb = *(const float4*)(wp + 4);
        float wc = wp[8];
        float ws[9] = {wa.x, wa.y, wa.z, wa.w, wb.x, wb.y, wb.z, wb.w, wc};
        u64 ww[9];
        #pragma unroll
        for (int t = 0; t < 9; t++) ww[t] = f2bcast(ws[t]);

        #pragma unroll
        for (int iy = 0; iy < 5; iy++) {
            u64 r[5];
            #pragma unroll
            for (int ix = 0; ix < 5; ix++) r[ix] = hp[iy * 5 + ix];
            #pragma unroll
            for (int dy = 0; dy < 3; dy++) {
                const int y = iy + 1 - dy;
                if (y >= 0 && y < 5) {
                    #pragma unroll
                    for (int x = 0; x < 5; x++)
                        #pragma unroll
                        for (int dx = 0; dx < 3; dx++) {
                            const int ix = x + dx - 1;
                            if (ix >= 0 && ix < 5)
                                acc[y*5 + x] = f2fma(ww[dy*3 + dx], r[ix], acc[y*5 + x]);
                        }
                }
            }
        }
    }

    #pragma unroll
    for (int i = 0; i < 25; i++) {
        float lo, hi; f2unpack(acc[i], lo, hi);
        lo = fmaxf(lo, 0.0f); hi = fmaxf(hi, 0.0f);
        ((u64*)hout)[i] = f2pack(lo, hi);
    }
}

__global__ __launch_bounds__(NTHREADS, 2)
void Kpcnn_49160195670356_kernel(const float* __restrict__ gin,
                                 const float* __restrict__ w0,
                                 const float* __restrict__ b0,
                                 const float* __restrict__ wmid,
                                 const float* __restrict__ bmid,
                                 const float* __restrict__ wlast,
                                 const float* __restrict__ blast,
                                 const float* __restrict__ wpost,
                                 const float* __restrict__ bpost,
                                 float* __restrict__ gout)
{
    extern __shared__ float smem[];
    float* hA     = smem;                // H_BUF
    float* hB     = hA + H_BUF;          // H_BUF
    float* wbuf   = hB + H_BUF;          // W_BUF
    float* bbuf   = wbuf + W_BUF;        // 64
    float* colorsS= bbuf + 64;           // [2 half][NPAIR][18]

    const int tid  = threadIdx.x;
    const int pair = tid / 25;
    const int oc   = tid % 25;
    const bool act = (tid < NPAIR * 25);
    const long pg  = (long)blockIdx.x * PPB;

    // ---- stage input (pair-interleaved), conv0 weights (padded rows), wpost, b0 ----
    for (int i = tid; i < PPB * 200; i += NTHREADS) {
        const int patch = i / 200;
        const int rem   = i % 200;
        const int c     = rem / 25;
        const int pos   = rem % 25;
        const float v = gin[(pg + patch) * 200 + rem];
        hB[((patch >> 1) * 25 + c) * PLANE + pos * 2 + (patch & 1)] = v;
    }
    for (int i = tid; i < 25 * 8 * 9; i += NTHREADS)
        wbuf[(i / 9) * 12 + (i % 9)] = w0[i];
    for (int i = tid; i < 18 * 75; i += NTHREADS)
        wbuf[WPOST_OFF + i] = wpost[i];
    if (tid < 25) bbuf[tid] = b0[tid];
    __syncthreads();

    // ---- colors (VALID 5x5 conv on input ch 0..2) : threads (pair, t<18) ----
    if (act && oc < 18) {
        u64 a2 = f2bcast(__ldg(bpost + oc));
        const float* wp = wbuf + WPOST_OFF + oc * 75;
        #pragma unroll 1
        for (int c = 0; c < 3; c++) {
            const u64* ip = (const u64*)(hB + (pair * 25 + c) * PLANE);
            #pragma unroll
            for (int k = 0; k < 25; k++)
                a2 = f2fma(f2bcast(wp[c * 25 + k]), ip[k], a2);
        }
        float lo, hi; f2unpack(a2, lo, hi);
        colorsS[pair * 18 + oc] = lo;
        colorsS[NPAIR * 18 + pair * 18 + oc] = hi;
    }

    // ---- conv0: hB(8ch) -> hA ----
    if (act)
        conv_pair<8>(hB + pair * 25 * PLANE, wbuf + oc * 8 * 12, bbuf[oc],
                     hA + (pair * 25 + oc) * PLANE);

    // ---- mid layers, ping-pong ----
    float* bufs[2] = { hA, hB };
    int cur = 0;
    #pragma unroll 1
    for (int layer = 0; layer < NUM_MID; layer++) {
        __syncthreads();
        const float* wg = wmid + (long)layer * 5625;
        for (int i = tid; i < 5625; i += NTHREADS)
            wbuf[(i / 9) * 12 + (i % 9)] = wg[i];
        if (tid < 25) bbuf[tid] = bmid[layer * 25 + tid];
        __syncthreads();
        if (act)
            conv_pair<25>(bufs[cur] + pair * PBLK, wbuf + oc * 25 * 12, bbuf[oc],
                          bufs[cur ^ 1] + (pair * 25 + oc) * PLANE);
        cur ^= 1;
    }

    __syncthreads();
    // ---- stage last-layer weights pre-packed as pairs: [6*25 rows][10 pairs] ----
    for (int i = tid; i < 6 * 25 * 9; i += NTHREADS) {
        const int row = i / 9, t = i % 9;
        const float v = wlast[i];
        wbuf[(row * 10 + t) * 2 + 0] = v;
        wbuf[(row * 10 + t) * 2 + 1] = v;
    }
    if (tid < 6) bbuf[tid] = blast[tid];
    __syncthreads();

    // ---- last conv (25->6) per position + softmax + einsum ----
    if (act) {
        const int j = oc;
        const int y = j / 5, x = j % 5;
        const float* hfin = bufs[cur] + pair * PBLK;

        int  off[9];
        bool inb[9];
        #pragma unroll
        for (int dy = 0; dy < 3; dy++)
            #pragma unroll
            for (int dx = 0; dx < 3; dx++) {
                const int iy = y + dy - 1, ix = x + dx - 1;
                const int t = dy * 3 + dx;
                inb[t] = (iy >= 0 && iy < 5 && ix >= 0 && ix < 5);
                off[t] = inb[t] ? (iy * 5 + ix) : 0;
            }

        u64 s[6];
        #pragma unroll
        for (int w = 0; w < 6; w++) s[w] = f2bcast(bbuf[w]);

        #pragma unroll 1
        for (int ic = 0; ic < 25; ic++) {
            const u64* hp = (const u64*)(hfin + ic * PLANE);
            u64 v[9];
            #pragma unroll
            for (int t = 0; t < 9; t++) v[t] = inb[t] ? hp[off[t]] : 0ULL;
            #pragma unroll
            for (int w = 0; w < 6; w++) {
                const u64* wl = ((const u64*)wbuf) + (w * 25 + ic) * 10;
                #pragma unroll
                for (int t = 0; t < 9; t++) s[w] = f2fma(wl[t], v[t], s[w]);
            }
        }

        #pragma unroll
        for (int half = 0; half < 2; half++) {
            float sv[6];
            #pragma unroll
            for (int w = 0; w < 6; w++) {
                float lo, hi; f2unpack(s[w], lo, hi);
                sv[w] = half ? hi : lo;
            }
            float m = sv[0];
            #pragma unroll
            for (int w = 1; w < 6; w++) m = fmaxf(m, sv[w]);
            float e[6], sum = 0.0f;
            #pragma unroll
            for (int w = 0; w < 6; w++) { e[w] = __expf(sv[w] - m); sum += e[w]; }
            const float inv = 1.0f / sum;

            const float* col = colorsS + half * (NPAIR * 18) + pair * 18;
            const long ob = (pg + 2 * pair + half) * 75;
            #pragma unroll
            for (int c = 0; c < 3; c++) {
                float r = 0.0f;
                #pragma unroll
                for (int w = 0; w < 6; w++) r = fmaf(col[c * 6 + w], e[w], r);
                gout[ob + c * 25 + j] = r * inv;
            }
        }
    }
}

extern "C" void kernel_launch(void* const* d_in, const int* in_sizes, int n_in,
                              void* d_out, int out_size)
{
    const float* gin   = (const float*)d_in[0];
    const float* w0    = (const float*)d_in[1];
    const float* b0    = (const float*)d_in[2];
    const float* wmid  = (const float*)d_in[3];
    const float* bmid  = (const float*)d_in[4];
    const float* wlast = (const float*)d_in[5];
    const float* blast = (const float*)d_in[6];
    const float* wpost = (const float*)d_in[7];
    const float* bpost = (const float*)d_in[8];
    float* gout = (float*)d_out;

    cudaFuncSetAttribute(Kpcnn_49160195670356_kernel,
                         cudaFuncAttributeMaxDynamicSharedMemorySize, SMEM_BYTES);

    Kpcnn_49160195670356_kernel<<<B_TOTAL / PPB, NTHREADS, SMEM_BYTES>>>(
        gin, w0, b0, wmid, bmid, wlast, blast, wpost, bpost, gout);
}

// round 3
// speedup vs baseline: 2.1201x; 1.0322x over previous
#include <cuda_runtime.h>

typedef unsigned long long u64;

#define B_TOTAL  32768
#define NUM_MID  6
#define PPB      16          // patches per block (8 pairs)
#define NPAIR    8
#define NTHREADS 224         // 8*25 = 200 active

// SMEM layout (floats). Plane: 5 rows x 12 floats (row = 5 pair-packed positions + pad)
#define PLANE_F   60
#define ROW_F     12
#define H_BUF     (NPAIR*25*PLANE_F)        // 12000 floats
#define W_BUF     5625                      // [25oc][25ic][9] unpadded
#define WPOST_OFF 1800                      // conv0 weights occupy [0,1800)
#define SMEM_FLOATS (H_BUF + W_BUF + 64 + 2*NPAIR*18)
#define SMEM_BYTES  (SMEM_FLOATS*4)

// ---- f32x2 helpers ----
__device__ __forceinline__ u64 f2pack(float lo, float hi) {
    u64 r; asm("mov.b64 %0,{%1,%2};" : "=l"(r) : "f"(lo), "f"(hi)); return r;
}
__device__ __forceinline__ u64 f2bcast(float v) { return f2pack(v, v); }
__device__ __forceinline__ void f2unpack(u64 a, float& lo, float& hi) {
    asm("mov.b64 {%0,%1},%2;" : "=f"(lo), "=f"(hi) : "l"(a));
}
__device__ __forceinline__ u64 f2fma(u64 a, u64 b, u64 c) {
    u64 d; asm("fma.rn.f32x2 %0,%1,%2,%3;" : "=l"(d) : "l"(a), "l"(b), "l"(c)); return d;
}

// Accumulate 3x3 SAME conv on 5x5 pair-packed planes into registers (no writes).
// hin: [CIN][PLANE_F] this pair; wrow: [CIN][9] this oc.
template<int CIN>
__device__ __forceinline__ void conv_accum(const float* __restrict__ hin,
                                           const float* __restrict__ wrow,
                                           float bias,
                                           u64 acc[25])
{
    const u64 b2 = f2bcast(bias);
    #pragma unroll
    for (int i = 0; i < 25; i++) acc[i] = b2;

    #pragma unroll 1
    for (int ic = 0; ic < CIN; ic++) {
        const float* wp = wrow + ic * 9;
        u64 ww[9];
        #pragma unroll
        for (int t = 0; t < 9; t++) ww[t] = f2bcast(wp[t]);

        const float* plane = hin + ic * PLANE_F;
        #pragma unroll
        for (int iy = 0; iy < 5; iy++) {
            const ulonglong2* rp = (const ulonglong2*)(plane + iy * ROW_F);
            ulonglong2 q0 = rp[0];
            ulonglong2 q1 = rp[1];
            u64 r[5];
            r[0] = q0.x; r[1] = q0.y; r[2] = q1.x; r[3] = q1.y;
            r[4] = *(const u64*)(plane + iy * ROW_F + 8);

            #pragma unroll
            for (int dy = 0; dy < 3; dy++) {
                const int y = iy + 1 - dy;
                if (y >= 0 && y < 5) {
                    #pragma unroll
                    for (int x = 0; x < 5; x++)
                        #pragma unroll
                        for (int dx = 0; dx < 3; dx++) {
                            const int ix = x + dx - 1;
                            if (ix >= 0 && ix < 5)
                                acc[y*5 + x] = f2fma(ww[dy*3 + dx], r[ix], acc[y*5 + x]);
                        }
                }
            }
        }
    }
}

__device__ __forceinline__ void relu_store(float* __restrict__ hout, const u64 acc[25])
{
    #pragma unroll
    for (int y = 0; y < 5; y++) {
        u64 o[5];
        #pragma unroll
        for (int x = 0; x < 5; x++) {
            float lo, hi; f2unpack(acc[y*5 + x], lo, hi);
            o[x] = f2pack(fmaxf(lo, 0.0f), fmaxf(hi, 0.0f));
        }
        ulonglong2* rp = (ulonglong2*)(hout + y * ROW_F);
        rp[0] = make_ulonglong2(o[0], o[1]);
        rp[1] = make_ulonglong2(o[2], o[3]);
        *(u64*)(hout + y * ROW_F + 8) = o[4];
    }
}

__global__ __launch_bounds__(NTHREADS, 3)
void Kpcnn_49160195670356_kernel(const float* __restrict__ gin,
                                 const float* __restrict__ w0,
                                 const float* __restrict__ b0,
                                 const float* __restrict__ wmid,
                                 const float* __restrict__ bmid,
                                 const float* __restrict__ wlast,
                                 const float* __restrict__ blast,
                                 const float* __restrict__ wpost,
                                 const float* __restrict__ bpost,
                                 float* __restrict__ gout)
{
    extern __shared__ float smem[];
    float* hbuf   = smem;                // H_BUF (single buffer, in-place layers)
    float* wbuf   = hbuf + H_BUF;        // W_BUF
    float* bbuf   = wbuf + W_BUF;        // 64
    float* colorsS= bbuf + 64;           // [2 half][NPAIR][18]

    const int tid  = threadIdx.x;
    const int pair = tid / 25;
    const int oc   = tid % 25;
    const bool act = (tid < NPAIR * 25);
    const long pg  = (long)blockIdx.x * PPB;

    // ---- stage input (pair-interleaved, padded rows), conv0 weights, wpost, b0 ----
    for (int i = tid; i < PPB * 200; i += NTHREADS) {
        const int patch = i / 200;
        const int rem   = i % 200;
        const int c     = rem / 25;
        const int pos   = rem % 25;
        const int y = pos / 5, x = pos % 5;
        const float v = gin[(pg + patch) * 200 + rem];
        hbuf[((patch >> 1) * 25 + c) * PLANE_F + y * ROW_F + x * 2 + (patch & 1)] = v;
    }
    for (int i = tid; i < 25 * 8 * 9; i += NTHREADS) wbuf[i] = w0[i];
    for (int i = tid; i < 18 * 75; i += NTHREADS) wbuf[WPOST_OFF + i] = wpost[i];
    if (tid < 25) bbuf[tid] = b0[tid];
    __syncthreads();

    // ---- colors (VALID 5x5 conv on input ch 0..2), reads input before conv0 overwrite ----
    if (act && oc < 18) {
        u64 a2 = f2bcast(__ldg(bpost + oc));
        const float* wp = wbuf + WPOST_OFF + oc * 75;
        #pragma unroll 1
        for (int c = 0; c < 3; c++) {
            const float* ip = hbuf + (pair * 25 + c) * PLANE_F;
            #pragma unroll
            for (int k = 0; k < 25; k++) {
                const u64 v = *(const u64*)(ip + (k / 5) * ROW_F + (k % 5) * 2);
                a2 = f2fma(f2bcast(wp[c * 25 + k]), v, a2);
            }
        }
        float lo, hi; f2unpack(a2, lo, hi);
        colorsS[pair * 18 + oc] = lo;
        colorsS[NPAIR * 18 + pair * 18 + oc] = hi;
    }

    // ---- conv0: 8ch -> 25ch, in place ----
    {
        u64 acc[25];
        if (act)
            conv_accum<8>(hbuf + pair * 25 * PLANE_F, wbuf + oc * 72, bbuf[oc], acc);
        __syncthreads();   // all reads of input (incl. colors) complete
        if (act)
            relu_store(hbuf + (pair * 25 + oc) * PLANE_F, acc);
        __syncthreads();
    }

    // ---- mid layers, in place ----
    #pragma unroll 1
    for (int layer = 0; layer < NUM_MID; layer++) {
        const float* wg = wmid + (long)layer * W_BUF;
        for (int i = tid; i < W_BUF; i += NTHREADS) wbuf[i] = wg[i];
        if (tid < 25) bbuf[tid] = bmid[layer * 25 + tid];
        __syncthreads();
        u64 acc[25];
        if (act)
            conv_accum<25>(hbuf + pair * 25 * PLANE_F, wbuf + oc * 225, bbuf[oc], acc);
        __syncthreads();
        if (act)
            relu_store(hbuf + (pair * 25 + oc) * PLANE_F, acc);
        __syncthreads();
    }

    // ---- stage last-layer weights pre-packed pairs: [(oc*25+ic)*10 + t] u64 ----
    for (int i = tid; i < 6 * 25 * 9; i += NTHREADS) {
        const int row = i / 9, t = i % 9;
        const float v = wlast[i];
        wbuf[(row * 10 + t) * 2 + 0] = v;
        wbuf[(row * 10 + t) * 2 + 1] = v;
    }
    if (tid < 6) bbuf[tid] = blast[tid];
    __syncthreads();

    // ---- last conv (25->6) per position + softmax + einsum ----
    if (act) {
        const int j = oc;
        const int y = j / 5, x = j % 5;
        const float* hfin = hbuf + pair * 25 * PLANE_F;

        int  off[9];
        bool inb[9];
        #pragma unroll
        for (int dy = 0; dy < 3; dy++)
            #pragma unroll
            for (int dx = 0; dx < 3; dx++) {
                const int iy = y + dy - 1, ix = x + dx - 1;
                const int t = dy * 3 + dx;
                inb[t] = (iy >= 0 && iy < 5 && ix >= 0 && ix < 5);
                off[t] = inb[t] ? (iy * ROW_F + ix * 2) : 0;
            }

        u64 s[6];
        #pragma unroll
        for (int w = 0; w < 6; w++) s[w] = f2bcast(bbuf[w]);

        #pragma unroll 1
        for (int ic = 0; ic < 25; ic++) {
            const float* hp = hfin + ic * PLANE_F;
            u64 v[9];
            #pragma unroll
            for (int t = 0; t < 9; t++) v[t] = inb[t] ? *(const u64*)(hp + off[t]) : 0ULL;
            #pragma unroll
            for (int w = 0; w < 6; w++) {
                const u64* wl = ((const u64*)wbuf) + (w * 25 + ic) * 10;
                #pragma unroll
                for (int t = 0; t < 9; t++) s[w] = f2fma(wl[t], v[t], s[w]);
            }
        }

        #pragma unroll
        for (int half = 0; half < 2; half++) {
            float sv[6];
            #pragma unroll
            for (int w = 0; w < 6; w++) {
                float lo, hi; f2unpack(s[w], lo, hi);
                sv[w] = half ? hi : lo;
            }
            float m = sv[0];
            #pragma unroll
            for (int w = 1; w < 6; w++) m = fmaxf(m, sv[w]);
            float e[6], sum = 0.0f;
            #pragma unroll
            for (int w = 0; w < 6; w++) { e[w] = __expf(sv[w] - m); sum += e[w]; }
            const float inv = 1.0f / sum;

            const float* col = colorsS + half * (NPAIR * 18) + pair * 18;
            const long ob = (pg + 2 * pair + half) * 75;
            #pragma unroll
            for (int c = 0; c < 3; c++) {
                float r = 0.0f;
                #pragma unroll
                for (int w = 0; w < 6; w++) r = fmaf(col[c * 6 + w], e[w], r);
                gout[ob + c * 25 + j] = r * inv;
            }
        }
    }
}

extern "C" void kernel_launch(void* const* d_in, const int* in_sizes, int n_in,
                              void* d_out, int out_size)
{
    const float* gin   = (const float*)d_in[0];
    const float* w0    = (const float*)d_in[1];
    const float* b0    = (const float*)d_in[2];
    const float* wmid  = (const float*)d_in[3];
    const float* bmid  = (const float*)d_in[4];
    const float* wlast = (const float*)d_in[5];
    const float* blast = (const float*)d_in[6];
    const float* wpost = (const float*)d_in[7];
    const float* bpost = (const float*)d_in[8];
    float* gout = (float*)d_out;

    cudaFuncSetAttribute(Kpcnn_49160195670356_kernel,
                         cudaFuncAttributeMaxDynamicSharedMemorySize, SMEM_BYTES);

    Kpcnn_49160195670356_kernel<<<B_TOTAL / PPB, NTHREADS, SMEM_BYTES>>>(
        gin, w0, b0, wmid, bmid, wlast, blast, wpost, bpost, gout);
}